// round 2
// baseline (speedup 1.0000x reference)
#include <cuda_runtime.h>
#include <cuda_bf16.h>
#include <math.h>

// Problem constants
#define BB 4
#define EE 8192
#define NN 1024
#define FF 512
#define DD 512
#define CAP 64          // max edges per source row (Poisson(8); P(>64) ~ 0)
#define MROWS (BB*NN)   // 4096

// Scratch (static device globals; no allocations)
__device__ float g_z[MROWS * DD];       // 8 MB
__device__ float g_a1[MROWS];
__device__ float g_a2[MROWS];
__device__ int   g_cnt[MROWS];
__device__ int   g_bucket[MROWS * CAP]; // packed (dst<<16)|e

// ---------------------------------------------------------------------------
// Kernel 0: zero per-row edge counters
// ---------------------------------------------------------------------------
__global__ void zero_cnt_kernel() {
    int i = blockIdx.x * blockDim.x + threadIdx.x;
    if (i < MROWS) g_cnt[i] = 0;
}

// ---------------------------------------------------------------------------
// Kernel 1: extract src/dst from one-hot rows (warp per edge, early exit),
//           scatter edge into per-(b,src) bucket.
// ---------------------------------------------------------------------------
__global__ void extract_kernel(const float* __restrict__ Cmat,
                               const float* __restrict__ Nmat) {
    int warp = (blockIdx.x * blockDim.x + threadIdx.x) >> 5;
    int lane = threadIdx.x & 31;
    if (warp >= BB * EE) return;
    int b = warp >> 13;              // E = 8192 = 2^13

    // --- scan Cmat row -> src ---
    const float4* c4 = (const float4*)(Cmat + (size_t)warp * NN);
    int found = -1;
    #pragma unroll 1
    for (int it = 0; it < NN / 128; it++) {
        float4 v = c4[it * 32 + lane];
        int loc = -1;
        if      (v.x > 0.5f) loc = 0;
        else if (v.y > 0.5f) loc = 1;
        else if (v.z > 0.5f) loc = 2;
        else if (v.w > 0.5f) loc = 3;
        if (loc >= 0) found = (it * 32 + lane) * 4 + loc;
        if (__ballot_sync(0xffffffffu, loc >= 0)) break;
    }
    int src = __reduce_max_sync(0xffffffffu, found);

    // --- scan Nmat row -> dst ---
    const float4* n4 = (const float4*)(Nmat + (size_t)warp * NN);
    found = -1;
    #pragma unroll 1
    for (int it = 0; it < NN / 128; it++) {
        float4 v = n4[it * 32 + lane];
        int loc = -1;
        if      (v.x > 0.5f) loc = 0;
        else if (v.y > 0.5f) loc = 1;
        else if (v.z > 0.5f) loc = 2;
        else if (v.w > 0.5f) loc = 3;
        if (loc >= 0) found = (it * 32 + lane) * 4 + loc;
        if (__ballot_sync(0xffffffffu, loc >= 0)) break;
    }
    int dst = __reduce_max_sync(0xffffffffu, found);

    if (lane == 0 && src >= 0 && dst >= 0) {
        int e   = warp & (EE - 1);
        int row = b * NN + src;
        int pos = atomicAdd(&g_cnt[row], 1);
        if (pos < CAP) g_bucket[row * CAP + pos] = (dst << 16) | e;
    }
}

// ---------------------------------------------------------------------------
// Kernel 2: z = nodes @ w   ([4096,512] x [512,512], fp32 tiled GEMM)
// 128x128 block tile, BK=16, 256 threads, 8x8 per-thread micro-tile.
// Packed fp32 pairs via fma.rn.f32x2 (2 FMAs per issue) + smem double buffer.
// ---------------------------------------------------------------------------
#define GBM 128
#define GBN 128
#define GBK 16

__device__ __forceinline__ unsigned long long pack_dup(float a) {
    unsigned long long r;
    asm("mov.b64 %0, {%1, %1};" : "=l"(r) : "f"(a));
    return r;
}
__device__ __forceinline__ void ffma2(unsigned long long& acc,
                                      unsigned long long a,
                                      unsigned long long b) {
    asm("fma.rn.f32x2 %0, %1, %2, %0;" : "+l"(acc) : "l"(a), "l"(b));
}

__global__ __launch_bounds__(256) void gemm_kernel(const float* __restrict__ A,
                                                   const float* __restrict__ Bw) {
    __shared__ __align__(16) float As[2][GBK][GBM];
    __shared__ __align__(16) float Bs[2][GBK][GBN];

    int tid = threadIdx.x;
    int bm = blockIdx.y * GBM;
    int bn = blockIdx.x * GBN;
    int tx = tid & 15;          // 0..15 (n dir)
    int ty = tid >> 4;          // 0..15 (m dir)

    // acc as f32x2 pairs: [m 0..7][n-pair 0..3]
    unsigned long long acc2[8][4];
    #pragma unroll
    for (int i = 0; i < 8; i++)
        #pragma unroll
        for (int j = 0; j < 4; j++) acc2[i][j] = 0ull;

    int arow  = tid >> 1;       // 0..127
    int ahalf = tid & 1;        // which 8-k half
    int brow  = tid >> 4;       // 0..15
    int bcol4 = tid & 15;       // 0..15 (+16 second pass)

    float4 pa[2], pb[2];

    // prologue: fetch tile 0
    #pragma unroll
    for (int q = 0; q < 2; q++)
        pa[q] = *(const float4*)&A[(size_t)(bm + arow) * FF + (ahalf * 2 + q) * 4];
    #pragma unroll
    for (int q = 0; q < 2; q++)
        pb[q] = *(const float4*)&Bw[(size_t)brow * DD + bn + (bcol4 + q * 16) * 4];

    #pragma unroll
    for (int q = 0; q < 2; q++) {
        int kc = (ahalf * 2 + q) * 4;
        As[0][kc + 0][arow] = pa[q].x;
        As[0][kc + 1][arow] = pa[q].y;
        As[0][kc + 2][arow] = pa[q].z;
        As[0][kc + 3][arow] = pa[q].w;
        *(float4*)&Bs[0][brow][(bcol4 + q * 16) * 4] = pb[q];
    }
    __syncthreads();

    const int NIT = FF / GBK;   // 32
    for (int it = 0; it < NIT; it++) {
        int buf = it & 1;
        // prefetch next tile to registers
        if (it + 1 < NIT) {
            int k0 = (it + 1) * GBK;
            #pragma unroll
            for (int q = 0; q < 2; q++)
                pa[q] = *(const float4*)&A[(size_t)(bm + arow) * FF + k0 + (ahalf * 2 + q) * 4];
            #pragma unroll
            for (int q = 0; q < 2; q++)
                pb[q] = *(const float4*)&Bw[(size_t)(k0 + brow) * DD + bn + (bcol4 + q * 16) * 4];
        }

        // compute on current buffer
        #pragma unroll
        for (int k = 0; k < GBK; k++) {
            float4 a0 = *(const float4*)&As[buf][k][ty * 4];
            float4 a1 = *(const float4*)&As[buf][k][64 + ty * 4];
            // b pairs directly from smem: 4 x f32x2
            ulonglong2 b0 = *(const ulonglong2*)&Bs[buf][k][tx * 4];
            ulonglong2 b1 = *(const ulonglong2*)&Bs[buf][k][64 + tx * 4];
            unsigned long long bv[4] = {b0.x, b0.y, b1.x, b1.y};
            float av[8] = {a0.x, a0.y, a0.z, a0.w, a1.x, a1.y, a1.z, a1.w};
            #pragma unroll
            for (int i = 0; i < 8; i++) {
                unsigned long long av2 = pack_dup(av[i]);
                #pragma unroll
                for (int j = 0; j < 4; j++)
                    ffma2(acc2[i][j], av2, bv[j]);
            }
        }

        // store prefetched tile into the other buffer
        if (it + 1 < NIT) {
            int nb = buf ^ 1;
            #pragma unroll
            for (int q = 0; q < 2; q++) {
                int kc = (ahalf * 2 + q) * 4;
                As[nb][kc + 0][arow] = pa[q].x;
                As[nb][kc + 1][arow] = pa[q].y;
                As[nb][kc + 2][arow] = pa[q].z;
                As[nb][kc + 3][arow] = pa[q].w;
                *(float4*)&Bs[nb][brow][(bcol4 + q * 16) * 4] = pb[q];
            }
            __syncthreads();
        }
    }

    // write out: unpack f32x2 pairs
    #pragma unroll
    for (int i = 0; i < 8; i++) {
        int r = bm + ((i < 4) ? (ty * 4 + i) : (64 + ty * 4 + (i - 4)));
        float2 p0 = *(float2*)&acc2[i][0];
        float2 p1 = *(float2*)&acc2[i][1];
        float2 p2 = *(float2*)&acc2[i][2];
        float2 p3 = *(float2*)&acc2[i][3];
        float4 v0 = make_float4(p0.x, p0.y, p1.x, p1.y);
        float4 v1 = make_float4(p2.x, p2.y, p3.x, p3.y);
        *(float4*)&g_z[(size_t)r * DD + bn + tx * 4]      = v0;
        *(float4*)&g_z[(size_t)r * DD + bn + 64 + tx * 4] = v1;
    }
}

// ---------------------------------------------------------------------------
// Kernel 3: a1[n] = z[n]·attn[0:D], a2[n] = z[n]·attn[D:2D]
// ---------------------------------------------------------------------------
__global__ void a12_kernel(const float* __restrict__ attn) {
    int row = blockIdx.x;
    int tid = threadIdx.x;
    const float* zr = &g_z[(size_t)row * DD];
    float s1 = 0.f, s2 = 0.f;
    for (int c = tid; c < DD; c += 128) {
        float v = zr[c];
        s1 += v * attn[c];
        s2 += v * attn[DD + c];
    }
    #pragma unroll
    for (int o = 16; o > 0; o >>= 1) {
        s1 += __shfl_down_sync(0xffffffffu, s1, o);
        s2 += __shfl_down_sync(0xffffffffu, s2, o);
    }
    __shared__ float w1[4], w2[4];
    if ((tid & 31) == 0) { w1[tid >> 5] = s1; w2[tid >> 5] = s2; }
    __syncthreads();
    if (tid == 0) {
        g_a1[row] = w1[0] + w1[1] + w1[2] + w1[3];
        g_a2[row] = w2[0] + w2[1] + w2[2] + w2[3];
    }
}

// ---------------------------------------------------------------------------
// Kernel 4: per source-row: dedup edges by dst, softmax with the
// (1-adj)*(-1e9) masking quirk, aggregate z rows, leaky_relu, write out.
// One block (128 threads) per (b, n) row.
// ---------------------------------------------------------------------------
__global__ __launch_bounds__(128) void row_kernel(float* __restrict__ out) {
    int row = blockIdx.x;       // b*N + n
    int b   = row >> 10;        // N = 1024
    int tid = threadIdx.x;

    __shared__ int   s_raw[CAP];
    __shared__ int   s_ent[CAP];
    __shared__ float s_att[CAP];
    __shared__ float s_wgt[CAP];
    __shared__ float red[128];

    int cnt = g_cnt[row];
    if (cnt > CAP) cnt = CAP;

    if (cnt == 0) {
        for (int c = tid; c < DD; c += 128)
            out[(size_t)row * DD + c] = 0.f;
        return;
    }

    if (tid < cnt) s_raw[tid] = g_bucket[row * CAP + tid];
    __syncthreads();

    // deterministic order: rank-sort by edge id (unique per row)
    if (tid < cnt) {
        int mye = s_raw[tid] & 0xFFFF;
        int rank = 0;
        for (int j = 0; j < cnt; j++)
            rank += ((s_raw[j] & 0xFFFF) < mye);
        s_ent[rank] = s_raw[tid];
    }
    __syncthreads();

    // per-edge attention logit: leaky_relu(a1[src] + a2[dst])
    float a1v = g_a1[row];
    if (tid < cnt) {
        int dst = s_ent[tid] >> 16;
        float x = a1v + g_a2[b * NN + dst];
        s_att[tid] = (x > 0.f) ? x : 0.2f * x;
    }
    __syncthreads();

    // dedup by dst: first occurrence owns (count c, score sum s)
    float logit = -INFINITY;
    int   c = 0;
    bool  first = false;
    if (tid < cnt) {
        int dst = s_ent[tid] >> 16;
        first = true;
        float s = 0.f;
        for (int j = 0; j < cnt; j++) {
            if ((s_ent[j] >> 16) == dst) {
                if (j < tid) first = false;
                c++;
                s += s_att[j];
            }
        }
        if (first) logit = s + (float)(1 - c) * (-1e9f);
    }

    // block max
    red[tid] = logit;
    __syncthreads();
    #pragma unroll
    for (int st = 64; st > 0; st >>= 1) {
        if (tid < st) red[tid] = fmaxf(red[tid], red[tid + st]);
        __syncthreads();
    }
    float m = red[0];
    __syncthreads();

    float ev = (logit == -INFINITY) ? 0.f : expf(logit - m);
    red[tid] = ev;
    __syncthreads();
    #pragma unroll
    for (int st = 64; st > 0; st >>= 1) {
        if (tid < st) red[tid] += red[tid + st];
        __syncthreads();
    }
    float Z = red[0];
    __syncthreads();

    if (tid < cnt) s_wgt[tid] = first ? ((float)c * ev / Z) : 0.f;
    __syncthreads();

    // out[row] = leaky_relu( sum_j w_j * z[b, dst_j] )
    float acc[4] = {0.f, 0.f, 0.f, 0.f};
    for (int j = 0; j < cnt; j++) {
        float w = s_wgt[j];
        if (w != 0.f) {
            const float* zr = &g_z[(size_t)(b * NN + (s_ent[j] >> 16)) * DD];
            #pragma unroll
            for (int i = 0; i < 4; i++)
                acc[i] += w * zr[tid + i * 128];
        }
    }
    #pragma unroll
    for (int i = 0; i < 4; i++) {
        float v = acc[i];
        v = (v > 0.f) ? v : 0.2f * v;
        out[(size_t)row * DD + tid + i * 128] = v;
    }
}

// ---------------------------------------------------------------------------
// Launch
// ---------------------------------------------------------------------------
extern "C" void kernel_launch(void* const* d_in, const int* in_sizes, int n_in,
                              void* d_out, int out_size) {
    const float* nodes = (const float*)d_in[0];  // [B,N,F]
    const float* Cmat  = (const float*)d_in[1];  // [B,E,N]
    const float* Nmat  = (const float*)d_in[2];  // [B,E,N]
    // d_in[3] = mask (unused)
    const float* w     = (const float*)d_in[4];  // [F,D]
    const float* attn  = (const float*)d_in[5];  // [2D,1]
    float* out = (float*)d_out;

    zero_cnt_kernel<<<(MROWS + 255) / 256, 256>>>();

    // B*E warps = 32768, 8 warps/block
    extract_kernel<<<(BB * EE * 32 + 255) / 256, 256>>>(Cmat, Nmat);

    dim3 ggrid(DD / GBN, MROWS / GBM);   // (4, 32)
    gemm_kernel<<<ggrid, 256>>>(nodes, w);

    a12_kernel<<<MROWS, 128>>>(attn);

    row_kernel<<<MROWS, 128>>>(out);
}

// round 17
// speedup vs baseline: 1.4580x; 1.4580x over previous
#include <cuda_runtime.h>
#include <cuda_bf16.h>
#include <math.h>

// Problem constants
#define BB 4
#define EE 8192
#define NN 1024
#define FF 512
#define DD 512
#define CAP 64          // max edges per source row (Poisson(8); P(>64) ~ 0)
#define MROWS (BB*NN)   // 4096

// Scratch (static device globals; zero-initialized at module load)
__device__ float g_z[MROWS * DD];       // 8 MB
__device__ float g_a1[MROWS];
__device__ float g_a2[MROWS];
__device__ int   g_cnt[MROWS];
__device__ int   g_bucket[MROWS * CAP]; // packed (dst<<16)|e

// ---------------------------------------------------------------------------
// Helper: find position of the 1.0 within two float4 (8 floats), else -1
// ---------------------------------------------------------------------------
__device__ __forceinline__ int onehot_loc8(float4 v0, float4 v1) {
    int loc = -1;
    if      (v0.x > 0.5f) loc = 0;
    else if (v0.y > 0.5f) loc = 1;
    else if (v0.z > 0.5f) loc = 2;
    else if (v0.w > 0.5f) loc = 3;
    else if (v1.x > 0.5f) loc = 4;
    else if (v1.y > 0.5f) loc = 5;
    else if (v1.z > 0.5f) loc = 6;
    else if (v1.w > 0.5f) loc = 7;
    return loc;
}

// ---------------------------------------------------------------------------
// Kernel 1: extract src/dst from one-hot rows (warp per edge, early exit,
//           2 float4 per lane per iteration), scatter into per-(b,src) bucket.
//           First chunks of BOTH rows issued up front for MLP.
// ---------------------------------------------------------------------------
__global__ void extract_kernel(const float* __restrict__ Cmat,
                               const float* __restrict__ Nmat) {
    int warp = (blockIdx.x * blockDim.x + threadIdx.x) >> 5;
    int lane = threadIdx.x & 31;
    if (warp >= BB * EE) return;
    int b = warp >> 13;              // E = 8192 = 2^13

    const float4* c4 = (const float4*)(Cmat + (size_t)warp * NN);
    const float4* n4 = (const float4*)(Nmat + (size_t)warp * NN);

    // issue first chunks of both rows (4 independent loads in flight)
    float4 c0 = c4[lane * 2];
    float4 c1 = c4[lane * 2 + 1];
    float4 m0 = n4[lane * 2];
    float4 m1 = n4[lane * 2 + 1];

    // --- scan Cmat row -> src ---
    int found = -1;
    {
        int loc = onehot_loc8(c0, c1);
        if (loc >= 0) found = (lane * 2) * 4 + loc;
        if (!__ballot_sync(0xffffffffu, loc >= 0)) {
            #pragma unroll 1
            for (int it = 1; it < 4; it++) {
                float4 v0 = c4[it * 64 + lane * 2];
                float4 v1 = c4[it * 64 + lane * 2 + 1];
                loc = onehot_loc8(v0, v1);
                if (loc >= 0) found = (it * 64 + lane * 2) * 4 + loc;
                if (__ballot_sync(0xffffffffu, loc >= 0)) break;
            }
        }
    }
    int src = __reduce_max_sync(0xffffffffu, found);

    // --- scan Nmat row -> dst ---
    found = -1;
    {
        int loc = onehot_loc8(m0, m1);
        if (loc >= 0) found = (lane * 2) * 4 + loc;
        if (!__ballot_sync(0xffffffffu, loc >= 0)) {
            #pragma unroll 1
            for (int it = 1; it < 4; it++) {
                float4 v0 = n4[it * 64 + lane * 2];
                float4 v1 = n4[it * 64 + lane * 2 + 1];
                loc = onehot_loc8(v0, v1);
                if (loc >= 0) found = (it * 64 + lane * 2) * 4 + loc;
                if (__ballot_sync(0xffffffffu, loc >= 0)) break;
            }
        }
    }
    int dst = __reduce_max_sync(0xffffffffu, found);

    if (lane == 0 && src >= 0 && dst >= 0) {
        int e   = warp & (EE - 1);
        int row = b * NN + src;
        int pos = atomicAdd(&g_cnt[row], 1);
        if (pos < CAP) g_bucket[row * CAP + pos] = (dst << 16) | e;
    }
}

// ---------------------------------------------------------------------------
// Kernel 2: z = nodes @ w   ([4096,512] x [512,512], fp32)
// 128x64 block tile, BK=16, 256 threads, 8x4 micro-tile, f32x2 FFMA pairs,
// smem double buffer, 2 CTAs/SM.
// ---------------------------------------------------------------------------
#define GBM 128
#define GBN 64
#define GBK 16

__device__ __forceinline__ unsigned long long pack_dup(float a) {
    unsigned long long r;
    asm("mov.b64 %0, {%1, %1};" : "=l"(r) : "f"(a));
    return r;
}
__device__ __forceinline__ void ffma2(unsigned long long& acc,
                                      unsigned long long a,
                                      unsigned long long b) {
    asm("fma.rn.f32x2 %0, %1, %2, %0;" : "+l"(acc) : "l"(a), "l"(b));
}

__global__ __launch_bounds__(256, 2) void gemm_kernel(const float* __restrict__ A,
                                                      const float* __restrict__ Bw) {
    __shared__ __align__(16) float As[2][GBK][GBM];
    __shared__ __align__(16) float Bs[2][GBK][GBN];

    int tid = threadIdx.x;
    int bm = blockIdx.y * GBM;
    int bn = blockIdx.x * GBN;
    int tx = tid & 15;          // 0..15 (n dir, 4 cols each)
    int ty = tid >> 4;          // 0..15 (m dir, 8 rows each)

    // acc as f32x2 pairs: [m 0..7][n-pair 0..1]
    unsigned long long acc2[8][2];
    #pragma unroll
    for (int i = 0; i < 8; i++) {
        acc2[i][0] = 0ull; acc2[i][1] = 0ull;
    }

    int arow  = tid >> 1;       // 0..127
    int ahalf = tid & 1;        // which 8-k half
    int brow  = tid >> 4;       // 0..15
    int bcol4 = tid & 15;       // 0..15

    float4 pa[2], pb;

    // prologue: fetch tile 0
    #pragma unroll
    for (int q = 0; q < 2; q++)
        pa[q] = *(const float4*)&A[(size_t)(bm + arow) * FF + (ahalf * 2 + q) * 4];
    pb = *(const float4*)&Bw[(size_t)brow * DD + bn + bcol4 * 4];

    #pragma unroll
    for (int q = 0; q < 2; q++) {
        int kc = (ahalf * 2 + q) * 4;
        As[0][kc + 0][arow] = pa[q].x;
        As[0][kc + 1][arow] = pa[q].y;
        As[0][kc + 2][arow] = pa[q].z;
        As[0][kc + 3][arow] = pa[q].w;
    }
    *(float4*)&Bs[0][brow][bcol4 * 4] = pb;
    __syncthreads();

    const int NIT = FF / GBK;   // 32
    for (int it = 0; it < NIT; it++) {
        int buf = it & 1;
        // prefetch next tile to registers
        if (it + 1 < NIT) {
            int k0 = (it + 1) * GBK;
            #pragma unroll
            for (int q = 0; q < 2; q++)
                pa[q] = *(const float4*)&A[(size_t)(bm + arow) * FF + k0 + (ahalf * 2 + q) * 4];
            pb = *(const float4*)&Bw[(size_t)(k0 + brow) * DD + bn + bcol4 * 4];
        }

        // compute on current buffer
        #pragma unroll
        for (int k = 0; k < GBK; k++) {
            float4 a0 = *(const float4*)&As[buf][k][ty * 4];
            float4 a1 = *(const float4*)&As[buf][k][64 + ty * 4];
            ulonglong2 bu = *(const ulonglong2*)&Bs[buf][k][tx * 4];
            unsigned long long bv0 = bu.x, bv1 = bu.y;
            float av[8] = {a0.x, a0.y, a0.z, a0.w, a1.x, a1.y, a1.z, a1.w};
            #pragma unroll
            for (int i = 0; i < 8; i++) {
                unsigned long long av2 = pack_dup(av[i]);
                ffma2(acc2[i][0], av2, bv0);
                ffma2(acc2[i][1], av2, bv1);
            }
        }

        // store prefetched tile into the other buffer
        if (it + 1 < NIT) {
            int nb = buf ^ 1;
            #pragma unroll
            for (int q = 0; q < 2; q++) {
                int kc = (ahalf * 2 + q) * 4;
                As[nb][kc + 0][arow] = pa[q].x;
                As[nb][kc + 1][arow] = pa[q].y;
                As[nb][kc + 2][arow] = pa[q].z;
                As[nb][kc + 3][arow] = pa[q].w;
            }
            *(float4*)&Bs[nb][brow][bcol4 * 4] = pb;
            __syncthreads();
        }
    }

    // write out: unpack f32x2 pairs
    #pragma unroll
    for (int i = 0; i < 8; i++) {
        int r = bm + ((i < 4) ? (ty * 4 + i) : (64 + ty * 4 + (i - 4)));
        float2 p0 = *(float2*)&acc2[i][0];
        float2 p1 = *(float2*)&acc2[i][1];
        float4 v = make_float4(p0.x, p0.y, p1.x, p1.y);
        *(float4*)&g_z[(size_t)r * DD + bn + tx * 4] = v;
    }
}

// ---------------------------------------------------------------------------
// Kernel 3: a1[n] = z[n]·attn[0:D], a2[n] = z[n]·attn[D:2D]
// One warp per row, float4 loads, shuffle reduce.
// ---------------------------------------------------------------------------
__global__ __launch_bounds__(256) void a12_kernel(const float* __restrict__ attn) {
    int warp = (blockIdx.x * blockDim.x + threadIdx.x) >> 5;
    int lane = threadIdx.x & 31;
    if (warp >= MROWS) return;

    const float4* zr = (const float4*)&g_z[(size_t)warp * DD];
    const float4* A1 = (const float4*)attn;
    const float4* A2 = (const float4*)(attn + DD);

    float s1 = 0.f, s2 = 0.f;
    #pragma unroll
    for (int q = 0; q < 4; q++) {
        float4 z = zr[lane + 32 * q];
        float4 a = A1[lane + 32 * q];
        float4 c = A2[lane + 32 * q];
        s1 += z.x * a.x + z.y * a.y + z.z * a.z + z.w * a.w;
        s2 += z.x * c.x + z.y * c.y + z.z * c.z + z.w * c.w;
    }
    #pragma unroll
    for (int o = 16; o > 0; o >>= 1) {
        s1 += __shfl_down_sync(0xffffffffu, s1, o);
        s2 += __shfl_down_sync(0xffffffffu, s2, o);
    }
    if (lane == 0) {
        g_a1[warp] = s1;
        g_a2[warp] = s2;
    }
}

// ---------------------------------------------------------------------------
// Kernel 4: per source-row: dedup edges by dst, softmax with the
// (1-adj)*(-1e9) masking quirk, aggregate z rows, leaky_relu, write out.
// One block (128 threads) per (b, n) row. Resets g_cnt for next call.
// ---------------------------------------------------------------------------
__global__ __launch_bounds__(128) void row_kernel(float* __restrict__ out) {
    int row = blockIdx.x;       // b*N + n
    int b   = row >> 10;        // N = 1024
    int tid = threadIdx.x;

    __shared__ int   s_raw[CAP];
    __shared__ int   s_ent[CAP];
    __shared__ float s_att[CAP];
    __shared__ float s_wgt[CAP];
    __shared__ float red[128];

    int cnt = g_cnt[row];
    if (cnt > CAP) cnt = CAP;

    if (cnt == 0) {
        for (int c = tid; c < DD; c += 128)
            out[(size_t)row * DD + c] = 0.f;
        return;                 // g_cnt[row] already 0
    }

    if (tid < cnt) s_raw[tid] = g_bucket[row * CAP + tid];
    __syncthreads();

    // deterministic order: rank-sort by edge id (unique per row)
    if (tid < cnt) {
        int mye = s_raw[tid] & 0xFFFF;
        int rank = 0;
        for (int j = 0; j < cnt; j++)
            rank += ((s_raw[j] & 0xFFFF) < mye);
        s_ent[rank] = s_raw[tid];
    }
    __syncthreads();

    // per-edge attention logit: leaky_relu(a1[src] + a2[dst])
    float a1v = g_a1[row];
    if (tid < cnt) {
        int dst = s_ent[tid] >> 16;
        float x = a1v + g_a2[b * NN + dst];
        s_att[tid] = (x > 0.f) ? x : 0.2f * x;
    }
    __syncthreads();

    // dedup by dst: first occurrence owns (count c, score sum s)
    float logit = -INFINITY;
    int   c = 0;
    bool  first = false;
    if (tid < cnt) {
        int dst = s_ent[tid] >> 16;
        first = true;
        float s = 0.f;
        for (int j = 0; j < cnt; j++) {
            if ((s_ent[j] >> 16) == dst) {
                if (j < tid) first = false;
                c++;
                s += s_att[j];
            }
        }
        if (first) logit = s + (float)(1 - c) * (-1e9f);
    }

    // block max
    red[tid] = logit;
    __syncthreads();
    #pragma unroll
    for (int st = 64; st > 0; st >>= 1) {
        if (tid < st) red[tid] = fmaxf(red[tid], red[tid + st]);
        __syncthreads();
    }
    float m = red[0];
    __syncthreads();

    float ev = (logit == -INFINITY) ? 0.f : expf(logit - m);
    red[tid] = ev;
    __syncthreads();
    #pragma unroll
    for (int st = 64; st > 0; st >>= 1) {
        if (tid < st) red[tid] += red[tid + st];
        __syncthreads();
    }
    float Z = red[0];
    __syncthreads();

    if (tid < cnt) s_wgt[tid] = first ? ((float)c * ev / Z) : 0.f;
    __syncthreads();

    // out[row] = leaky_relu( sum_j w_j * z[b, dst_j] )
    float acc[4] = {0.f, 0.f, 0.f, 0.f};
    for (int j = 0; j < cnt; j++) {
        float w = s_wgt[j];
        if (w != 0.f) {
            const float* zr = &g_z[(size_t)(b * NN + (s_ent[j] >> 16)) * DD];
            #pragma unroll
            for (int i = 0; i < 4; i++)
                acc[i] += w * zr[tid + i * 128];
        }
    }
    #pragma unroll
    for (int i = 0; i < 4; i++) {
        float v = acc[i];
        v = (v > 0.f) ? v : 0.2f * v;
        out[(size_t)row * DD + tid + i * 128] = v;
    }

    // reset counter for next call (deterministic; globals start zeroed)
    if (tid == 0) g_cnt[row] = 0;
}

// ---------------------------------------------------------------------------
// Launch: fork extract (DRAM-bound) || gemm->a12 (fma-bound), join for row.
// ---------------------------------------------------------------------------
static cudaStream_t s_side = nullptr;
static cudaEvent_t  s_fork = nullptr, s_join = nullptr;

extern "C" void kernel_launch(void* const* d_in, const int* in_sizes, int n_in,
                              void* d_out, int out_size) {
    const float* nodes = (const float*)d_in[0];  // [B,N,F]
    const float* Cmat  = (const float*)d_in[1];  // [B,E,N]
    const float* Nmat  = (const float*)d_in[2];  // [B,E,N]
    // d_in[3] = mask (unused)
    const float* w     = (const float*)d_in[4];  // [F,D]
    const float* attn  = (const float*)d_in[5];  // [2D,1]
    float* out = (float*)d_out;

    if (s_side == nullptr) {
        cudaStreamCreateWithFlags(&s_side, cudaStreamNonBlocking);
        cudaEventCreateWithFlags(&s_fork, cudaEventDisableTiming);
        cudaEventCreateWithFlags(&s_join, cudaEventDisableTiming);
    }

    // fork side stream off the main stream
    cudaEventRecord(s_fork, 0);
    cudaStreamWaitEvent(s_side, s_fork, 0);

    // side stream: gemm -> a12 (compute-bound chain)
    dim3 ggrid(DD / GBN, MROWS / GBM);   // (8, 32) = 256 blocks
    gemm_kernel<<<ggrid, 256, 0, s_side>>>(nodes, w);
    a12_kernel<<<MROWS / 8, 256, 0, s_side>>>(attn);   // 4096 warps

    // main stream: extraction (memory-bound), concurrent with gemm
    extract_kernel<<<(BB * EE) / 8, 256>>>(Cmat, Nmat);

    // join
    cudaEventRecord(s_join, s_side);
    cudaStreamWaitEvent(0, s_join, 0);

    row_kernel<<<MROWS, 128>>>(out);
}